// round 1
// baseline (speedup 1.0000x reference)
#include <cuda_runtime.h>
#include <cstddef>

// BranchRoute: score = sigmoid(x @ W_gate + b); hot_i = score_i > 0.5  <=>  logit_i > 0.
// out = concat(x_0, x_1, x_0 + x_1), each [N, D] f32.
// Single pass: one block per token row; x is loaded once into registers (float4/thread),
// reused for the gate reduction AND all three output stores. HBM traffic = 64MB R + 192MB W.

constexpr int D = 1024;
constexpr int THREADS = 256;   // 256 * 4 floats = 1024 = D

__global__ __launch_bounds__(THREADS) void branch_route_kernel(
    const float* __restrict__ x,
    const float* __restrict__ Wg,    // [D, 2] row-major: Wg[k*2 + branch]
    const float* __restrict__ bg,    // [2]
    float* __restrict__ out,         // [3, N, D]
    int n_tokens)
{
    const int row = blockIdx.x;
    const int t   = threadIdx.x;

    // Load this thread's 4 elements of the row (coalesced 128B per warp-quarter).
    const size_t row_base = (size_t)row * D;
    const float4 v = reinterpret_cast<const float4*>(x + row_base)[t];

    // W slice for k = 4t..4t+3: 8 contiguous floats = two float4.
    // w01 = {w[4t,0], w[4t,1], w[4t+1,0], w[4t+1,1]}, w23 likewise.
    const float4 w01 = __ldg(reinterpret_cast<const float4*>(Wg) + 2 * t);
    const float4 w23 = __ldg(reinterpret_cast<const float4*>(Wg) + 2 * t + 1);

    float s0 = v.x * w01.x + v.y * w01.z + v.z * w23.x + v.w * w23.z;
    float s1 = v.x * w01.y + v.y * w01.w + v.z * w23.y + v.w * w23.w;

    // Warp tree-reduce both partials.
    #pragma unroll
    for (int o = 16; o > 0; o >>= 1) {
        s0 += __shfl_xor_sync(0xFFFFFFFFu, s0, o);
        s1 += __shfl_xor_sync(0xFFFFFFFFu, s1, o);
    }

    __shared__ float sh0[8];
    __shared__ float sh1[8];
    const int wid = t >> 5;
    if ((t & 31) == 0) { sh0[wid] = s0; sh1[wid] = s1; }
    __syncthreads();

    float l0 = __ldg(&bg[0]);
    float l1 = __ldg(&bg[1]);
    #pragma unroll
    for (int i = 0; i < 8; i++) { l0 += sh0[i]; l1 += sh1[i]; }

    // sigmoid(l) > 0.5  <=>  l > 0
    const bool h0 = l0 > 0.0f;
    const bool h1 = l1 > 0.0f;

    const float4 zero = make_float4(0.f, 0.f, 0.f, 0.f);
    const float4 o0 = h0 ? v : zero;
    const float4 o1 = h1 ? v : zero;
    float4 oc;
    oc.x = o0.x + o1.x;
    oc.y = o0.y + o1.y;
    oc.z = o0.z + o1.z;
    oc.w = o0.w + o1.w;

    const size_t plane = (size_t)n_tokens * D;
    float4* outv = reinterpret_cast<float4*>(out);
    const size_t idx = (row_base >> 2) + t;            // float4 index within a plane
    outv[idx]                   = o0;
    outv[(plane >> 2) + idx]    = o1;
    outv[2 * (plane >> 2) + idx] = oc;
}

extern "C" void kernel_launch(void* const* d_in, const int* in_sizes, int n_in,
                              void* d_out, int out_size)
{
    const float* x  = (const float*)d_in[0];   // [N, D]
    const float* Wg = (const float*)d_in[1];   // [D, 2]
    const float* bg = (const float*)d_in[2];   // [2]
    float* out      = (float*)d_out;           // [3, N, D]

    const int n_tokens = in_sizes[0] / D;      // 16384

    branch_route_kernel<<<n_tokens, THREADS>>>(x, Wg, bg, out, n_tokens);
}

// round 2
// speedup vs baseline: 1.1533x; 1.1533x over previous
#include <cuda_runtime.h>
#include <cstddef>

// BranchRoute single-pass, L1-wavefront-optimized.
// hot_i = sigmoid(logit_i) > 0.5  <=>  logit_i > 0.
// 8 rows per block: W_gate lives in registers across the row loop (amortizes
// the 8KB gate-weight read that previously cost 64 L1 wavefronts PER ROW).
// Block reduce: warp shfl -> 1 STS (float2) -> 1 LDS -> 3-level shfl broadcast.

constexpr int D        = 1024;
constexpr int THREADS  = 256;   // 256 * 4 floats = 1024 = D
constexpr int ROWS     = 8;     // rows per block

__global__ __launch_bounds__(THREADS) void branch_route_kernel(
    const float* __restrict__ x,
    const float* __restrict__ Wg,    // [D, 2] row-major: Wg[k*2 + branch]
    const float* __restrict__ bg,    // [2]
    float* __restrict__ out,         // [3, N, D]
    int n_tokens)
{
    const int t    = threadIdx.x;
    const int lane = t & 31;
    const int wid  = t >> 5;

    // Gate weights for k = 4t..4t+3, resident in registers for all ROWS rows.
    // w01 = {w[4t,0], w[4t,1], w[4t+1,0], w[4t+1,1]}, w23 likewise.
    const float4* Wg4 = reinterpret_cast<const float4*>(Wg);
    const float4 w01 = __ldg(Wg4 + 2 * t);
    const float4 w23 = __ldg(Wg4 + 2 * t + 1);
    const float  b0  = __ldg(&bg[0]);
    const float  b1  = __ldg(&bg[1]);

    __shared__ float2 sh[2][8];      // ping-pong per-warp partials {s0, s1}

    const float4* xv   = reinterpret_cast<const float4*>(x);
    float4*       outv = reinterpret_cast<float4*>(out);
    const size_t  plane4 = (size_t)n_tokens * (D / 4);

    int p = 0;
    #pragma unroll
    for (int r = 0; r < ROWS; r++) {
        const int    row = blockIdx.x * ROWS + r;
        const size_t idx = (size_t)row * (D / 4) + t;

        // x read once, streaming (no reuse).
        const float4 v = __ldcs(xv + idx);

        float s0 = v.x * w01.x + v.y * w01.z + v.z * w23.x + v.w * w23.z;
        float s1 = v.x * w01.y + v.y * w01.w + v.z * w23.y + v.w * w23.w;

        // Warp butterfly: all lanes end with the warp total.
        #pragma unroll
        for (int o = 16; o > 0; o >>= 1) {
            s0 += __shfl_xor_sync(0xFFFFFFFFu, s0, o);
            s1 += __shfl_xor_sync(0xFFFFFFFFu, s1, o);
        }

        if (lane == 0) sh[p][wid] = make_float2(s0, s1);
        __syncthreads();

        // Each lane grabs one of the 8 warp partials; 3-level butterfly within
        // each group of 8 lanes sums them -> every lane holds the row logits.
        float2 pv = sh[p][lane & 7];
        float l0 = pv.x, l1 = pv.y;
        #pragma unroll
        for (int o = 4; o > 0; o >>= 1) {
            l0 += __shfl_xor_sync(0xFFFFFFFFu, l0, o);
            l1 += __shfl_xor_sync(0xFFFFFFFFu, l1, o);
        }
        l0 += b0;
        l1 += b1;

        const bool h0 = l0 > 0.0f;   // sigmoid(l) > 0.5  <=>  l > 0
        const bool h1 = l1 > 0.0f;

        const float4 zero = make_float4(0.f, 0.f, 0.f, 0.f);
        const float4 o0 = h0 ? v : zero;
        const float4 o1 = h1 ? v : zero;
        float4 oc;
        oc.x = o0.x + o1.x;
        oc.y = o0.y + o1.y;
        oc.z = o0.z + o1.z;
        oc.w = o0.w + o1.w;

        // Streaming stores: outputs are never re-read.
        __stcs(outv + idx,               o0);
        __stcs(outv + plane4 + idx,      o1);
        __stcs(outv + 2 * plane4 + idx,  oc);

        p ^= 1;
    }
}

extern "C" void kernel_launch(void* const* d_in, const int* in_sizes, int n_in,
                              void* d_out, int out_size)
{
    const float* x  = (const float*)d_in[0];   // [N, D]
    const float* Wg = (const float*)d_in[1];   // [D, 2]
    const float* bg = (const float*)d_in[2];   // [2]
    float* out      = (float*)d_out;           // [3, N, D]

    const int n_tokens = in_sizes[0] / D;      // 16384
    const int blocks   = n_tokens / ROWS;      // 2048

    branch_route_kernel<<<blocks, THREADS>>>(x, Wg, bg, out, n_tokens);
}

// round 4
// speedup vs baseline: 1.3153x; 1.1404x over previous
#include <cuda_runtime.h>
#include <cstddef>

// BranchRoute single-pass, MLP-optimized.
// hot_i = sigmoid(logit_i) > 0.5  <=>  logit_i > 0.
// 8 rows/block: all 8 row loads front-batched into registers (MLP=8/warp),
// then ONE value-splitting butterfly reduces all 16 partials in 16 shfls,
// two __syncthreads total, flags broadcast as one 16-bit ballot mask.

constexpr int D       = 1024;
constexpr int THREADS = 256;    // 256 * 4 floats = 1024 = D
constexpr int ROWS    = 8;

__global__ __launch_bounds__(THREADS) void branch_route_kernel(
    const float* __restrict__ x,
    const float* __restrict__ Wg,    // [D, 2]: Wg[k*2 + branch]
    const float* __restrict__ bg,    // [2]
    float* __restrict__ out,         // [3, N, D]
    int n_tokens)
{
    const int t    = threadIdx.x;
    const int lane = t & 31;
    const int wid  = t >> 5;

    // Gate weights for dims 4t..4t+3, register-resident (L1/L2 hit after wave 1).
    const float4* Wg4 = reinterpret_cast<const float4*>(Wg);
    const float4 w01 = __ldg(Wg4 + 2 * t);
    const float4 w23 = __ldg(Wg4 + 2 * t + 1);

    const float4* xv     = reinterpret_cast<const float4*>(x);
    float4*       outv   = reinterpret_cast<float4*>(out);
    const size_t  plane4 = (size_t)n_tokens * (D / 4);
    const size_t  base   = (size_t)blockIdx.x * ROWS * (D / 4) + t;

    // ---- Phase 1: front-batched loads (8 independent LDG.128 in flight) ----
    float4 v[ROWS];
    #pragma unroll
    for (int r = 0; r < ROWS; r++)
        v[r] = __ldcs(xv + base + (size_t)r * (D / 4));

    // ---- Phase 2: per-thread partial dots: 16 values (8 rows x 2 branches) ----
    float s[16];
    #pragma unroll
    for (int r = 0; r < ROWS; r++) {
        s[2*r]   = v[r].x * w01.x + v[r].y * w01.z + v[r].z * w23.x + v[r].w * w23.z;
        s[2*r+1] = v[r].x * w01.y + v[r].y * w01.w + v[r].z * w23.y + v[r].w * w23.w;
    }

    // ---- Phase 3: value-splitting butterfly: 16 values -> 16 shfls total ----
    // At each level, half the values are exchanged; lane l ends holding the
    // warp total of value v = (l>>1)&15 (duplicated across lane pairs).
    #define LVL(O, V)                                                          \
    {                                                                          \
        const bool up = (lane & (O)) != 0;                                     \
        _Pragma("unroll")                                                      \
        for (int i = 0; i < (V) / 2; i++) {                                    \
            const float send = up ? s[i] : s[i + (V) / 2];                     \
            const float got  = __shfl_xor_sync(0xFFFFFFFFu, send, (O));        \
            s[i] = (up ? s[i + (V) / 2] : s[i]) + got;                         \
        }                                                                      \
    }
    LVL(16, 16)
    LVL(8,  8)
    LVL(4,  4)
    LVL(2,  2)
    s[0] += __shfl_xor_sync(0xFFFFFFFFu, s[0], 1);   // final pair merge
    #undef LVL

    // ---- Phase 4: cross-warp reduce + flag mask (2 barriers total) ----
    __shared__ float    shp[8][16];     // [warp][value]  (conflict-free)
    __shared__ unsigned smask;

    if ((lane & 1) == 0) shp[wid][(lane >> 1) & 15] = s[0];
    __syncthreads();

    if (wid == 0) {
        float tot = 0.0f;
        if (lane < 16) {
            #pragma unroll
            for (int w = 0; w < 8; w++) tot += shp[w][lane];
            tot += __ldg(&bg[lane & 1]);
        }
        const unsigned m = __ballot_sync(0xFFFFFFFFu, (lane < 16) && (tot > 0.0f));
        if (lane == 0) smask = m;       // bit (2r+c) = hot flag of row r, branch c
    }
    __syncthreads();

    const unsigned m = smask;

    // ---- Phase 5: 24 streaming stores from registers ----
    #pragma unroll
    for (int r = 0; r < ROWS; r++) {
        const bool h0 = (m >> (2 * r)) & 1u;
        const bool h1 = (m >> (2 * r + 1)) & 1u;

        const float4 zero = make_float4(0.f, 0.f, 0.f, 0.f);
        const float4 o0 = h0 ? v[r] : zero;
        const float4 o1 = h1 ? v[r] : zero;
        float4 oc;
        oc.x = o0.x + o1.x;
        oc.y = o0.y + o1.y;
        oc.z = o0.z + o1.z;
        oc.w = o0.w + o1.w;

        const size_t idx = base + (size_t)r * (D / 4);
        __stcs(outv + idx,               o0);
        __stcs(outv + plane4 + idx,      o1);
        __stcs(outv + 2 * plane4 + idx,  oc);
    }
}

extern "C" void kernel_launch(void* const* d_in, const int* in_sizes, int n_in,
                              void* d_out, int out_size)
{
    const float* x  = (const float*)d_in[0];   // [N, D]
    const float* Wg = (const float*)d_in[1];   // [D, 2]
    const float* bg = (const float*)d_in[2];   // [2]
    float* out      = (float*)d_out;           // [3, N, D]

    const int n_tokens = in_sizes[0] / D;      // 16384
    const int blocks   = n_tokens / ROWS;      // 2048

    branch_route_kernel<<<blocks, THREADS>>>(x, Wg, bg, out, n_tokens);
}